// round 2
// baseline (speedup 1.0000x reference)
#include <cuda_runtime.h>
#include <cuda_bf16.h>
#include <cstdint>

#define N_U 100000
#define N_I 100000
#define NE  500000
#define H   128
#define D_U 256
#define D_I 300
#define NN  100000           // N_U == N_I
#define NUH (N_U * H)        // 12,800,000

// ---------------- scratch (static device globals; no allocation) -------------
__device__ float g_hu[2][NUH];     // user features ping-pong
__device__ float g_hi[2][NUH];     // item features ping-pong
__device__ float g_S[3][NUH];      // scatter accumulators: 0=uu, 1=iu, 2=ui
__device__ float g_deg[6][NN];     // 0 rout_uu, 1 rin_uu, 2 rout_ui, 3 rin_ui, 4 rout_iu, 5 rin_iu

// ---------------- utility kernels -------------------------------------------
__global__ void zero_kernel(float4* p, long long n4) {
    long long i = (long long)blockIdx.x * blockDim.x + threadIdx.x;
    long long stride = (long long)gridDim.x * blockDim.x;
    for (; i < n4; i += stride) p[i] = make_float4(0.f, 0.f, 0.f, 0.f);
}

__global__ void deg_count_kernel(const int* __restrict__ suu, const int* __restrict__ duu,
                                 const int* __restrict__ sui, const int* __restrict__ dui,
                                 const int* __restrict__ siu, const int* __restrict__ diu,
                                 float* __restrict__ deg) {
    int i = blockIdx.x * blockDim.x + threadIdx.x;
    if (i >= NE) return;
    atomicAdd(&deg[0 * NN + suu[i]], 1.f);
    atomicAdd(&deg[1 * NN + duu[i]], 1.f);
    atomicAdd(&deg[2 * NN + sui[i]], 1.f);
    atomicAdd(&deg[3 * NN + dui[i]], 1.f);
    atomicAdd(&deg[4 * NN + siu[i]], 1.f);
    atomicAdd(&deg[5 * NN + diu[i]], 1.f);
}

__global__ void deg_finalize_kernel(float* __restrict__ deg) {
    int i = blockIdx.x * blockDim.x + threadIdx.x;
    if (i >= NN) return;
#pragma unroll
    for (int j = 0; j < 6; j++) {
        float d = deg[j * NN + i];
        deg[j * NN + i] = rsqrtf(fmaxf(d, 1.f));
    }
}

// ---------------- edge scatter: S[dst] += X[src] * rout[src] -----------------
// one warp per edge; 32 lanes x float4 = full 128-float row
__global__ __launch_bounds__(256) void scatter_kernel(
    const float* __restrict__ X, const float* __restrict__ rout,
    const int* __restrict__ src, const int* __restrict__ dst,
    float* __restrict__ S) {
    int e = blockIdx.x * 8 + (threadIdx.x >> 5);
    if (e >= NE) return;
    int lane = threadIdx.x & 31;
    int s = __ldg(&src[e]);
    int d = __ldg(&dst[e]);
    float r = __ldg(&rout[s]);
    float4 v = *(const float4*)(X + (size_t)s * H + lane * 4);
    float* out = S + (size_t)d * H + lane * 4;
    asm volatile("red.global.add.v4.f32 [%0], {%1, %2, %3, %4};"
                 :: "l"(out), "f"(v.x * r), "f"(v.y * r), "f"(v.z * r), "f"(v.w * r)
                 : "memory");
}

// ---------------- SGEMM: C[M,128] = epi(A[M,K] @ W[K,128]) -------------------
// epi: v = acc * rowscale[row] + bias[col]; optional relu; optional C += v
// block tile 64x128, 256 threads, 8x4 per-thread micro-tile
#define BM 64
#define BN 128
#define BK 16

__global__ __launch_bounds__(256) void sgemm128_kernel(
    const float* __restrict__ A, const float* __restrict__ W,
    const float* __restrict__ bias, const float* __restrict__ rowscale,
    float* __restrict__ C, int M, int K, int doRelu, int accum) {
    __shared__ float As[BK][BM + 1];
    __shared__ float Bs[BK][BN];

    int block_row = blockIdx.x * BM;
    int tid = threadIdx.x;
    int tcol = (tid & 31) * 4;   // 0..124
    int trow = (tid >> 5) * 8;   // 0..56

    float acc[8][4];
#pragma unroll
    for (int i = 0; i < 8; i++)
#pragma unroll
        for (int j = 0; j < 4; j++) acc[i][j] = 0.f;

    int ktiles = (K + BK - 1) / BK;
    for (int t = 0; t < ktiles; ++t) {
        int k0 = t * BK;
        // load A tile (64 x 16)
#pragma unroll
        for (int i = tid; i < BM * BK; i += 256) {
            int m = i >> 4, kk = i & 15;
            int gm = block_row + m, gk = k0 + kk;
            As[kk][m] = (gm < M && gk < K) ? A[(size_t)gm * K + gk] : 0.f;
        }
        // load B tile (16 x 128)
#pragma unroll
        for (int i = tid; i < BK * BN; i += 256) {
            int kk = i >> 7, n = i & 127;
            int gk = k0 + kk;
            Bs[kk][n] = (gk < K) ? W[(size_t)gk * BN + n] : 0.f;
        }
        __syncthreads();
#pragma unroll
        for (int kk = 0; kk < BK; ++kk) {
            float4 bv = *(const float4*)&Bs[kk][tcol];
#pragma unroll
            for (int i = 0; i < 8; i++) {
                float a = As[kk][trow + i];
                acc[i][0] += a * bv.x;
                acc[i][1] += a * bv.y;
                acc[i][2] += a * bv.z;
                acc[i][3] += a * bv.w;
            }
        }
        __syncthreads();
    }

    float4 bb = *(const float4*)&bias[tcol];
#pragma unroll
    for (int i = 0; i < 8; i++) {
        int gm = block_row + trow + i;
        if (gm >= M) break;
        float rs = rowscale ? rowscale[gm] : 1.f;
        float4 v;
        v.x = acc[i][0] * rs + bb.x;
        v.y = acc[i][1] * rs + bb.y;
        v.z = acc[i][2] * rs + bb.z;
        v.w = acc[i][3] * rs + bb.w;
        if (doRelu) {
            v.x = fmaxf(v.x, 0.f); v.y = fmaxf(v.y, 0.f);
            v.z = fmaxf(v.z, 0.f); v.w = fmaxf(v.w, 0.f);
        }
        float4* cp = (float4*)(C + (size_t)gm * BN + tcol);
        if (accum) {
            float4 old = *cp;
            v.x += old.x; v.y += old.y; v.z += old.z; v.w += old.w;
        }
        *cp = v;
    }
}

// ---------------- host orchestration -----------------------------------------
extern "C" void kernel_launch(void* const* d_in, const int* in_sizes, int n_in,
                              void* d_out, int out_size) {
    const float* feat_user = (const float*)d_in[0];
    const float* feat_item = (const float*)d_in[1];
    const int* src_uu = (const int*)d_in[2];
    const int* dst_uu = (const int*)d_in[3];
    const int* src_ui = (const int*)d_in[4];
    const int* dst_ui = (const int*)d_in[5];
    const int* src_iu = (const int*)d_in[6];
    const int* dst_iu = (const int*)d_in[7];
    const float* We_u = (const float*)d_in[8];
    const float* be_u = (const float*)d_in[9];
    const float* We_i = (const float*)d_in[10];
    const float* be_i = (const float*)d_in[11];
    // per-layer params start at 12: (W_uu, b_uu, W_ui, b_ui, W_iu, b_iu) x 3
    const float* W[3][3];   // [layer][etype: 0=uu, 1=ui, 2=iu]
    const float* B[3][3];
    for (int l = 0; l < 3; l++) {
        for (int e = 0; e < 3; e++) {
            W[l][e] = (const float*)d_in[12 + l * 6 + e * 2];
            B[l][e] = (const float*)d_in[12 + l * 6 + e * 2 + 1];
        }
    }

    float *hu, *hi, *S, *deg;
    cudaGetSymbolAddress((void**)&hu, g_hu);
    cudaGetSymbolAddress((void**)&hi, g_hi);
    cudaGetSymbolAddress((void**)&S, g_S);
    cudaGetSymbolAddress((void**)&deg, g_deg);
    float* out = (float*)d_out;

    // degrees (exact integer-valued float adds -> deterministic)
    zero_kernel<<<256, 256>>>((float4*)deg, (long long)(6 * NN) / 4);
    deg_count_kernel<<<(NE + 255) / 256, 256>>>(src_uu, dst_uu, src_ui, dst_ui,
                                                src_iu, dst_iu, deg);
    deg_finalize_kernel<<<(NN + 255) / 256, 256>>>(deg);

    const float* rout_uu = deg + 0 * NN;
    const float* rin_uu  = deg + 1 * NN;
    const float* rout_ui = deg + 2 * NN;
    const float* rin_ui  = deg + 3 * NN;
    const float* rout_iu = deg + 4 * NN;
    const float* rin_iu  = deg + 5 * NN;

    int gemm_grid = (NN + BM - 1) / BM;

    // embed: hu = feat_user @ We_u + be_u ; hi = feat_item @ We_i + be_i
    sgemm128_kernel<<<gemm_grid, 256>>>(feat_user, We_u, be_u, nullptr,
                                        hu, NN, D_U, 0, 0);
    sgemm128_kernel<<<gemm_grid, 256>>>(feat_item, We_i, be_i, nullptr,
                                        hi, NN, D_I, 0, 0);

    int cur = 0;
    for (int l = 0; l < 3; l++) {
        int relu = (l < 2) ? 1 : 0;
        float* hu_cur = hu + (size_t)cur * NUH;
        float* hi_cur = hi + (size_t)cur * NUH;
        float* hu_nxt = (l == 2) ? out : hu + (size_t)(1 - cur) * NUH;
        float* hi_nxt = (l == 2) ? out + (size_t)NUH : hi + (size_t)(1 - cur) * NUH;
        float* Suu = S + 0 * (size_t)NUH;
        float* Siu = S + 1 * (size_t)NUH;
        float* Sui = S + 2 * (size_t)NUH;

        // zero the 3 scatter accumulators in one pass
        zero_kernel<<<2048, 256>>>((float4*)S, (long long)(3 * (size_t)NUH) / 4);

        // S[dst] += x[src] * rsqrt(deg_out[src])  (aggregation commutes with W)
        scatter_kernel<<<(NE + 7) / 8, 256>>>(hu_cur, rout_uu, src_uu, dst_uu, Suu);
        scatter_kernel<<<(NE + 7) / 8, 256>>>(hi_cur, rout_iu, src_iu, dst_iu, Siu);
        scatter_kernel<<<(NE + 7) / 8, 256>>>(hu_cur, rout_ui, src_ui, dst_ui, Sui);

        // hu_nxt = relu?(Suu@W_uu * rin_uu + b_uu) + relu?(Siu@W_iu * rin_iu + b_iu)
        sgemm128_kernel<<<gemm_grid, 256>>>(Suu, W[l][0], B[l][0], rin_uu,
                                            hu_nxt, NN, H, relu, 0);
        sgemm128_kernel<<<gemm_grid, 256>>>(Siu, W[l][2], B[l][2], rin_iu,
                                            hu_nxt, NN, H, relu, 1);
        // hi_nxt = relu?(Sui@W_ui * rin_ui + b_ui)
        sgemm128_kernel<<<gemm_grid, 256>>>(Sui, W[l][1], B[l][1], rin_ui,
                                            hi_nxt, NN, H, relu, 0);
        cur ^= 1;
    }
    (void)in_sizes; (void)n_in; (void)out_size;
}

// round 7
// speedup vs baseline: 1.5916x; 1.5916x over previous
#include <cuda_runtime.h>
#include <cuda_bf16.h>
#include <cstdint>

#define NN  100000
#define NE  500000
#define H   128
#define D_U 256
#define D_I 300
#define NUH (NN * H)

// ---------------- scratch (static device globals; no allocation) -------------
__device__ float g_hu[2][NUH];
__device__ float g_hi[2][NUH];
__device__ float g_S[3][NUH];      // 0=uu, 1=iu, 2=ui
__device__ float g_deg[6][NN];     // rout_uu, rin_uu, rout_ui, rin_ui, rout_iu, rin_iu

// ---------------- small helpers ----------------------------------------------
__device__ __forceinline__ uint32_t smem_u32(const void* p) {
    uint32_t a;
    asm("{ .reg .u64 t; cvta.to.shared.u64 t, %1; cvt.u32.u64 %0, t; }" : "=r"(a) : "l"(p));
    return a;
}

__device__ __forceinline__ void ldm_x4(uint32_t* r, uint32_t addr) {
    asm volatile("ldmatrix.sync.aligned.m8n8.x4.shared.b16 {%0,%1,%2,%3}, [%4];"
                 : "=r"(r[0]), "=r"(r[1]), "=r"(r[2]), "=r"(r[3]) : "r"(addr));
}
__device__ __forceinline__ void ldm_x4_t(uint32_t* r, uint32_t addr) {
    asm volatile("ldmatrix.sync.aligned.m8n8.x4.trans.shared.b16 {%0,%1,%2,%3}, [%4];"
                 : "=r"(r[0]), "=r"(r[1]), "=r"(r[2]), "=r"(r[3]) : "r"(addr));
}
__device__ __forceinline__ void mma_bf16(float* d, const uint32_t* a, uint32_t b0, uint32_t b1) {
    asm volatile("mma.sync.aligned.m16n8k16.row.col.f32.bf16.bf16.f32 "
                 "{%0,%1,%2,%3}, {%4,%5,%6,%7}, {%8,%9}, {%0,%1,%2,%3};"
                 : "+f"(d[0]), "+f"(d[1]), "+f"(d[2]), "+f"(d[3])
                 : "r"(a[0]), "r"(a[1]), "r"(a[2]), "r"(a[3]), "r"(b0), "r"(b1));
}

// exact Dekker-style bf16 split of two floats: returns packed hi bf16x2, residuals out
__device__ __forceinline__ void split2(float a, float b, uint32_t& hi, float& ra, float& rb) {
    __nv_bfloat16 ha = __float2bfloat16(a), hb = __float2bfloat16(b);
    hi = (uint32_t)__bfloat16_as_ushort(ha) | ((uint32_t)__bfloat16_as_ushort(hb) << 16);
    ra = a - __bfloat162float(ha);
    rb = b - __bfloat162float(hb);
}
__device__ __forceinline__ uint32_t pack2(float a, float b) {
    return (uint32_t)__bfloat16_as_ushort(__float2bfloat16(a)) |
           ((uint32_t)__bfloat16_as_ushort(__float2bfloat16(b)) << 16);
}

// ---------------- utility kernels -------------------------------------------
__global__ void zero_kernel(float4* p, long long n4) {
    long long i = (long long)blockIdx.x * blockDim.x + threadIdx.x;
    long long stride = (long long)gridDim.x * blockDim.x;
    for (; i < n4; i += stride) p[i] = make_float4(0.f, 0.f, 0.f, 0.f);
}

__global__ void deg_count_kernel(const int* __restrict__ suu, const int* __restrict__ duu,
                                 const int* __restrict__ sui, const int* __restrict__ dui,
                                 const int* __restrict__ siu, const int* __restrict__ diu,
                                 float* __restrict__ deg) {
    int i = blockIdx.x * blockDim.x + threadIdx.x;
    if (i >= NE) return;
    atomicAdd(&deg[0 * NN + suu[i]], 1.f);
    atomicAdd(&deg[1 * NN + duu[i]], 1.f);
    atomicAdd(&deg[2 * NN + sui[i]], 1.f);
    atomicAdd(&deg[3 * NN + dui[i]], 1.f);
    atomicAdd(&deg[4 * NN + siu[i]], 1.f);
    atomicAdd(&deg[5 * NN + diu[i]], 1.f);
}

__global__ void deg_finalize_kernel(float* __restrict__ deg) {
    int i = blockIdx.x * blockDim.x + threadIdx.x;
    if (i >= NN) return;
#pragma unroll
    for (int j = 0; j < 6; j++) {
        float d = deg[j * NN + i];
        deg[j * NN + i] = rsqrtf(fmaxf(d, 1.f));
    }
}

// ---------------- edge scatter: S[dst] += X[src] * rout[src] -----------------
__global__ __launch_bounds__(256) void scatter_kernel(
    const float* __restrict__ X, const float* __restrict__ rout,
    const int* __restrict__ src, const int* __restrict__ dst,
    float* __restrict__ S) {
    int e = blockIdx.x * 8 + (threadIdx.x >> 5);
    if (e >= NE) return;
    int lane = threadIdx.x & 31;
    int s = __ldg(&src[e]);
    int d = __ldg(&dst[e]);
    float r = __ldg(&rout[s]);
    float4 v = *(const float4*)(X + (size_t)s * H + lane * 4);
    float* out = S + (size_t)d * H + lane * 4;
    asm volatile("red.global.add.v4.f32 [%0], {%1, %2, %3, %4};"
                 :: "l"(out), "f"(v.x * r), "f"(v.y * r), "f"(v.z * r), "f"(v.w * r)
                 : "memory");
}

// ---------------- bf16x3-split tensor-core GEMM ------------------------------
// C[M,128] = epi( A[M,K] @ W[K,128] ),  epi(x) = maybe_relu(x*rs[row] + bias[col])
// optional accum: C += epi(...)
// CTA: 128(M) x 128(N), 256 thr, 8 warps of 32x64; K chunked by 32, dbl-buffered.
#define ABUF 10240                 // 128 rows * 80B (stride-80 kills ldmatrix conflicts)
#define BBUF 8192                  // 32 rows * 256B (XOR chunk swizzle)
#define BUFSZ (2 * ABUF + 2 * BBUF)
#define SM_BIAS (2 * BUFSZ)
#define TCSMEM (SM_BIAS + 512)

__global__ __launch_bounds__(256, 2) void mma_gemm_kernel(
    const float* __restrict__ A, const float* __restrict__ W,
    const float* __restrict__ bias, const float* __restrict__ rowscale,
    float* __restrict__ C, int M, int K, int doRelu, int accum)
{
    extern __shared__ char sm[];
    const uint32_t sbase = smem_u32(sm);
    const int tid = threadIdx.x, lane = tid & 31, wid = tid >> 5;
    const int blockRow = blockIdx.x * 128;
    const int wm = (wid & 3) * 32;      // warp M offset in tile
    const int wn = (wid >> 2) * 64;     // warp N offset in tile

    if (tid < 128) ((float*)(sm + SM_BIAS))[tid] = bias[tid];

    float acc[2][8][4];
#pragma unroll
    for (int i = 0; i < 2; i++)
#pragma unroll
        for (int j = 0; j < 8; j++)
#pragma unroll
            for (int k = 0; k < 4; k++) acc[i][j][k] = 0.f;

    const int nch = (K + 31) / 32;

    // per-lane ldmatrix address components
    const int r8 = lane & 7, sel = lane >> 3;
    const int a_row = r8 + ((sel & 1) << 3);     // row within 16-row tile
    const int a_kb  = (sel >> 1) << 4;           // 16B column select (k 0-7 vs 8-15)
    const int b_csel = sel >> 1;                 // n-chunk select within n16 tile

    // chunk loader: gmem fp32 -> bf16 hi/lo -> smem buffer (ch&1)
    auto load_chunk = [&](int ch) {
        const int k0 = ch * 32;
        char* buf = sm + (ch & 1) * BUFSZ;
        // A tile: 128 rows x 32 k
#pragma unroll
        for (int i = 0; i < 4; i++) {
            int idx = tid + i * 256;
            int row = idx >> 3, q = idx & 7;
            int gm = blockRow + row, gk = k0 + q * 4;
            float4 v = make_float4(0.f, 0.f, 0.f, 0.f);
            if (gm < M) {
                const float* ap = A + (size_t)gm * K + gk;
                if (gk + 3 < K) v = *(const float4*)ap;
                else {
                    if (gk + 0 < K) v.x = ap[0];
                    if (gk + 1 < K) v.y = ap[1];
                    if (gk + 2 < K) v.z = ap[2];
                    if (gk + 3 < K) v.w = ap[3];
                }
            }
            float rx, ry, rz, rw;
            uint2 hi, lo;
            split2(v.x, v.y, hi.x, rx, ry);
            split2(v.z, v.w, hi.y, rz, rw);
            lo.x = pack2(rx, ry);
            lo.y = pack2(rz, rw);
            *(uint2*)(buf + (size_t)row * 80 + q * 8) = hi;
            *(uint2*)(buf + ABUF + (size_t)row * 80 + q * 8) = lo;
        }
        // B tile: 32 k-rows x 128 n, XOR chunk swizzle
#pragma unroll
        for (int i = 0; i < 4; i++) {
            int idx = tid + i * 256;
            int kk = idx >> 5, q = idx & 31;
            int gk = k0 + kk;
            float4 v = make_float4(0.f, 0.f, 0.f, 0.f);
            if (gk < K) v = *(const float4*)(W + (size_t)gk * 128 + q * 4);
            float rx, ry, rz, rw;
            uint2 hi, lo;
            split2(v.x, v.y, hi.x, rx, ry);
            split2(v.z, v.w, hi.y, rz, rw);
            lo.x = pack2(rx, ry);
            lo.y = pack2(rz, rw);
            uint32_t off = (uint32_t)kk * 256 + ((((uint32_t)(q >> 1)) ^ (kk & 7)) << 4) + (q & 1) * 8;
            *(uint2*)(buf + 2 * ABUF + off) = hi;
            *(uint2*)(buf + 2 * ABUF + BBUF + off) = lo;
        }
    };

    load_chunk(0);
    __syncthreads();

    for (int ch = 0; ch < nch; ch++) {
        if (ch + 1 < nch) load_chunk(ch + 1);
        const uint32_t bufb = sbase + (ch & 1) * BUFSZ;

#pragma unroll
        for (int h = 0; h < 2; h++) {
            uint32_t ah[2][4], al[2][4], bf[4][4];
#pragma unroll
            for (int mt = 0; mt < 2; mt++) {
                uint32_t arow = wm + mt * 16 + a_row;
                uint32_t aaddr = bufb + arow * 80 + h * 32 + a_kb;
                ldm_x4(ah[mt], aaddr);
                ldm_x4(al[mt], aaddr + ABUF);
            }
            const int kk = h * 16 + a_row;  // same row formula for B k-row
            const uint32_t brow = bufb + 2 * ABUF + (uint32_t)kk * 256;
#pragma unroll
            for (int j = 0; j < 4; j++) {
                uint32_t chunk = (uint32_t)((wn >> 3) + j * 2 + b_csel) ^ (kk & 7);
                ldm_x4_t(bf[j], brow + chunk * 16);
            }
            // hi*hi and lo*hi
#pragma unroll
            for (int j = 0; j < 4; j++)
#pragma unroll
                for (int mt = 0; mt < 2; mt++) {
                    mma_bf16(acc[mt][2 * j],     ah[mt], bf[j][0], bf[j][1]);
                    mma_bf16(acc[mt][2 * j + 1], ah[mt], bf[j][2], bf[j][3]);
                    mma_bf16(acc[mt][2 * j],     al[mt], bf[j][0], bf[j][1]);
                    mma_bf16(acc[mt][2 * j + 1], al[mt], bf[j][2], bf[j][3]);
                }
            // hi*lo
#pragma unroll
            for (int j = 0; j < 4; j++) {
                uint32_t chunk = (uint32_t)((wn >> 3) + j * 2 + b_csel) ^ (kk & 7);
                ldm_x4_t(bf[j], brow + BBUF + chunk * 16);
            }
#pragma unroll
            for (int j = 0; j < 4; j++)
#pragma unroll
                for (int mt = 0; mt < 2; mt++) {
                    mma_bf16(acc[mt][2 * j],     ah[mt], bf[j][0], bf[j][1]);
                    mma_bf16(acc[mt][2 * j + 1], ah[mt], bf[j][2], bf[j][3]);
                }
        }
        __syncthreads();
    }

    // ---------------- epilogue -----------------------------------------------
    const float* bs = (const float*)(sm + SM_BIAS);
    const int g = lane >> 2;
    const int t2 = (lane & 3) * 2;
#pragma unroll
    for (int mt = 0; mt < 2; mt++) {
        int row0 = blockRow + wm + mt * 16 + g;
#pragma unroll
        for (int half = 0; half < 2; half++) {
            int row = row0 + half * 8;
            if (row >= M) continue;
            float rv = rowscale ? __ldg(&rowscale[row]) : 1.f;
            float* cp = C + (size_t)row * 128;
#pragma unroll
            for (int nt = 0; nt < 8; nt++) {
                int col = wn + nt * 8 + t2;
                float v0 = acc[mt][nt][half * 2 + 0] * rv + bs[col];
                float v1 = acc[mt][nt][half * 2 + 1] * rv + bs[col + 1];
                if (doRelu) { v0 = fmaxf(v0, 0.f); v1 = fmaxf(v1, 0.f); }
                if (accum) {
                    float2 o = *(const float2*)(cp + col);
                    v0 += o.x; v1 += o.y;
                }
                *(float2*)(cp + col) = make_float2(v0, v1);
            }
        }
    }
}

// ---------------- host orchestration -----------------------------------------
extern "C" void kernel_launch(void* const* d_in, const int* in_sizes, int n_in,
                              void* d_out, int out_size) {
    const float* feat_user = (const float*)d_in[0];
    const float* feat_item = (const float*)d_in[1];
    const int* src_uu = (const int*)d_in[2];
    const int* dst_uu = (const int*)d_in[3];
    const int* src_ui = (const int*)d_in[4];
    const int* dst_ui = (const int*)d_in[5];
    const int* src_iu = (const int*)d_in[6];
    const int* dst_iu = (const int*)d_in[7];
    const float* We_u = (const float*)d_in[8];
    const float* be_u = (const float*)d_in[9];
    const float* We_i = (const float*)d_in[10];
    const float* be_i = (const float*)d_in[11];
    const float* W[3][3];   // [layer][etype: 0=uu, 1=ui, 2=iu]
    const float* B[3][3];
    for (int l = 0; l < 3; l++)
        for (int e = 0; e < 3; e++) {
            W[l][e] = (const float*)d_in[12 + l * 6 + e * 2];
            B[l][e] = (const float*)d_in[12 + l * 6 + e * 2 + 1];
        }

    float *hu, *hi, *S, *deg;
    cudaGetSymbolAddress((void**)&hu, g_hu);
    cudaGetSymbolAddress((void**)&hi, g_hi);
    cudaGetSymbolAddress((void**)&S, g_S);
    cudaGetSymbolAddress((void**)&deg, g_deg);
    float* out = (float*)d_out;

    cudaFuncSetAttribute(mma_gemm_kernel,
                         cudaFuncAttributeMaxDynamicSharedMemorySize, TCSMEM);

    // degrees (exact integer-valued float adds -> deterministic)
    zero_kernel<<<256, 256>>>((float4*)deg, (long long)(6 * NN) / 4);
    deg_count_kernel<<<(NE + 255) / 256, 256>>>(src_uu, dst_uu, src_ui, dst_ui,
                                                src_iu, dst_iu, deg);
    deg_finalize_kernel<<<(NN + 255) / 256, 256>>>(deg);

    const float* rout_uu = deg + 0 * NN;
    const float* rin_uu  = deg + 1 * NN;
    const float* rout_ui = deg + 2 * NN;
    const float* rin_ui  = deg + 3 * NN;
    const float* rout_iu = deg + 4 * NN;
    const float* rin_iu  = deg + 5 * NN;

    int grid = (NN + 127) / 128;

    // embed
    mma_gemm_kernel<<<grid, 256, TCSMEM>>>(feat_user, We_u, be_u, nullptr,
                                           hu, NN, D_U, 0, 0);
    mma_gemm_kernel<<<grid, 256, TCSMEM>>>(feat_item, We_i, be_i, nullptr,
                                           hi, NN, D_I, 0, 0);

    int cur = 0;
    for (int l = 0; l < 3; l++) {
        int relu = (l < 2) ? 1 : 0;
        float* hu_cur = hu + (size_t)cur * NUH;
        float* hi_cur = hi + (size_t)cur * NUH;
        float* hu_nxt = (l == 2) ? out : hu + (size_t)(1 - cur) * NUH;
        float* hi_nxt = (l == 2) ? out + (size_t)NUH : hi + (size_t)(1 - cur) * NUH;
        float* Suu = S + 0 * (size_t)NUH;
        float* Siu = S + 1 * (size_t)NUH;
        float* Sui = S + 2 * (size_t)NUH;

        zero_kernel<<<2048, 256>>>((float4*)S, (long long)(3 * (size_t)NUH) / 4);

        scatter_kernel<<<(NE + 7) / 8, 256>>>(hu_cur, rout_uu, src_uu, dst_uu, Suu);
        scatter_kernel<<<(NE + 7) / 8, 256>>>(hi_cur, rout_iu, src_iu, dst_iu, Siu);
        scatter_kernel<<<(NE + 7) / 8, 256>>>(hu_cur, rout_ui, src_ui, dst_ui, Sui);

        // hu_nxt = relu?(Suu@W_uu*rin_uu+b_uu) + relu?(Siu@W_iu*rin_iu+b_iu)
        mma_gemm_kernel<<<grid, 256, TCSMEM>>>(Suu, W[l][0], B[l][0], rin_uu,
                                               hu_nxt, NN, H, relu, 0);
        mma_gemm_kernel<<<grid, 256, TCSMEM>>>(Siu, W[l][2], B[l][2], rin_iu,
                                               hu_nxt, NN, H, relu, 1);
        // hi_nxt = relu?(Sui@W_ui*rin_ui+b_ui)
        mma_gemm_kernel<<<grid, 256, TCSMEM>>>(Sui, W[l][1], B[l][1], rin_ui,
                                               hi_nxt, NN, H, relu, 0);
        cur ^= 1;
    }
    (void)in_sizes; (void)n_in; (void)out_size;
}